// round 12
// baseline (speedup 1.0000x reference)
#include <cuda_runtime.h>
#include <cuda_bf16.h>
#include <cstdint>
#include <math.h>

// ---------------------------------------------------------------------------
// BehavioralRotaryAttentionV25: B=2, L=2048, D=1024, H=16, hd=64 (fp32 I/O)
// R12: flash at 3 CTAs/SM (Q-fragments reloaded from SMEM, launch_bounds
// (128,3)); single fused cvt launch. GEMMs unchanged.
// ---------------------------------------------------------------------------

#define B_ 2
#define L_ 2048
#define D_ 1024
#define H_ 16
#define HD_ 64
#define M_ (B_*L_)
#define BHLHD (B_*H_*L_*HD_)

__device__ __nv_bfloat16 g_xbf [M_*D_];   // X bf16 [M][D]
__device__ __nv_bfloat16 g_wq  [D_*D_];
__device__ __nv_bfloat16 g_wk  [D_*D_];
__device__ __nv_bfloat16 g_wv  [D_*D_];
__device__ __nv_bfloat16 g_wo  [D_*D_];
__device__ __nv_bfloat16 g_q   [BHLHD];   // [b,h,l,d] (rotary, scaled 1/8)
__device__ __nv_bfloat16 g_k   [BHLHD];   // [b,h,l,d] (rotary)
__device__ __nv_bfloat16 g_vT  [BHLHD];   // [b,h,d,l]
__device__ __nv_bfloat16 g_ctx [M_*D_];   // [b,l,h,d] == [M][D]

// ------------------------- helpers -----------------------------------------
__device__ __forceinline__ void mma_bf16(float c[4], const uint32_t a[4],
                                         uint32_t b0, uint32_t b1) {
    asm volatile(
        "mma.sync.aligned.m16n8k16.row.col.f32.bf16.bf16.f32 "
        "{%0,%1,%2,%3}, {%4,%5,%6,%7}, {%8,%9}, {%0,%1,%2,%3};"
        : "+f"(c[0]), "+f"(c[1]), "+f"(c[2]), "+f"(c[3])
        : "r"(a[0]), "r"(a[1]), "r"(a[2]), "r"(a[3]), "r"(b0), "r"(b1));
}
__device__ __forceinline__ uint4 ldm_x4(uint32_t addr) {
    uint4 r;
    asm volatile("ldmatrix.sync.aligned.m8n8.x4.shared.b16 {%0,%1,%2,%3}, [%4];"
        : "=r"(r.x), "=r"(r.y), "=r"(r.z), "=r"(r.w) : "r"(addr));
    return r;
}
__device__ __forceinline__ uint32_t packbf(float lo, float hi) {
    __nv_bfloat162 h = __floats2bfloat162_rn(lo, hi);
    return *(uint32_t*)&h;
}
__device__ __forceinline__ uint32_t smem_u32(const void* p) {
    uint32_t a;
    asm("{ .reg .u64 t; cvta.to.shared.u64 t, %1; cvt.u32.u64 %0, t; }"
        : "=r"(a) : "l"(p));
    return a;
}
#define CP_ASYNC16(saddr, gptr) \
    asm volatile("cp.async.cg.shared.global [%0], [%1], 16;" \
        :: "r"((uint32_t)(saddr)), "l"(gptr) : "memory")
#define CP_COMMIT() asm volatile("cp.async.commit_group;" ::: "memory")
#define CP_WAIT1()  asm volatile("cp.async.wait_group 1;" ::: "memory")

// ---------------------------------------------------------------------------
// fused fp32 -> bf16 convert: X (1M uint2) + 4 weights (256K uint2 each).
// Single launch, range-partitioned.
// ---------------------------------------------------------------------------
#define NX4 (M_*D_/4)        // 1048576
#define NW4 (D_*D_/4)        // 262144

__global__ void __launch_bounds__(256) cvt_all(
    const float* __restrict__ X,
    const float* __restrict__ w0, const float* __restrict__ w1,
    const float* __restrict__ w2, const float* __restrict__ w3,
    __nv_bfloat16* __restrict__ xo,
    __nv_bfloat16* __restrict__ o0, __nv_bfloat16* __restrict__ o1,
    __nv_bfloat16* __restrict__ o2, __nv_bfloat16* __restrict__ o3)
{
    int i = blockIdx.x * 256 + threadIdx.x;
    const float* in;
    __nv_bfloat16* out;
    int off;
    if (i < NX4) {
        in = X; out = xo; off = i;
    } else {
        int j = i - NX4;
        int w = j >> 18;           // / NW4
        off = j & (NW4 - 1);
        in  = (w == 0) ? w0 : (w == 1) ? w1 : (w == 2) ? w2 : w3;
        out = (w == 0) ? o0 : (w == 1) ? o1 : (w == 2) ? o2 : o3;
    }
    float4 x = ((const float4*)in)[off];
    ((uint2*)out)[off] = make_uint2(packbf(x.x, x.y), packbf(x.z, x.w));
}

// ---------------------------------------------------------------------------
// bf16 GEMM (unchanged from R11): CTA 128x128, BK=64, double buffer.
// ---------------------------------------------------------------------------
#define GP 72
#define GTILE (128*GP*2)              // 18432 B per tile
#define GEMM_SMEM (2*2*GTILE)         // 73728 B

__global__ void __launch_bounds__(256, 2) gemm_bf16(
    const __nv_bfloat16* __restrict__ A,
    const __nv_bfloat16* __restrict__ W0, const __nv_bfloat16* __restrict__ W1,
    const __nv_bfloat16* __restrict__ W2,
    const float* __restrict__ b0v, const float* __restrict__ b1v,
    const float* __restrict__ b2v,
    const float* __restrict__ resid, const float* __restrict__ phi,
    void* __restrict__ out0, void* __restrict__ out1, void* __restrict__ out2,
    int qkv)
{
    extern __shared__ __align__(16) __nv_bfloat16 smem[];
    uint32_t sbu = smem_u32(smem);
    int tid = threadIdx.x, lane = tid & 31, wid = tid >> 5;
    int g = lane >> 2, t = lane & 3;
    int wm = wid >> 1, wn = wid & 1;
    int m0 = blockIdx.y * 128, n0 = blockIdx.x * 128;
    int z = blockIdx.z;

    const __nv_bfloat16* W = qkv ? ((z == 0) ? W0 : (z == 1) ? W1 : W2) : W0;
    const float* bias = qkv ? ((z == 0) ? b0v : (z == 1) ? b1v : b2v) : b0v;
    void* outv = qkv ? ((z == 0) ? out0 : (z == 1) ? out1 : out2) : out0;
    int mode = qkv ? ((z == 2) ? 2 : 1) : 0;
    float scale = (qkv && z == 0) ? 0.125f : 1.f;

    const __nv_bfloat16* Ab = A + (long)m0 * D_;
    const __nv_bfloat16* Wb = W + (long)n0 * D_;

    auto load_stage = [&](int kb) {
        int s = kb & 1;
        uint32_t abase = sbu + (uint32_t)(s * 2 * GTILE);
        uint32_t bbase = abase + GTILE;
        int k0 = kb * 64;
#pragma unroll
        for (int i = 0; i < 4; i++) {
            int idx = tid + i * 256;
            int row = idx >> 3, ch = idx & 7;
            uint32_t off = (uint32_t)(row * (GP * 2) + ch * 16);
            CP_ASYNC16(abase + off, Ab + (long)row * D_ + k0 + ch * 8);
            CP_ASYNC16(bbase + off, Wb + (long)row * D_ + k0 + ch * 8);
        }
        CP_COMMIT();
    };

    float acc[2][8][4];
#pragma unroll
    for (int mi = 0; mi < 2; mi++)
#pragma unroll
        for (int nj = 0; nj < 8; nj++)
#pragma unroll
            for (int x = 0; x < 4; x++) acc[mi][nj][x] = 0.f;

    load_stage(0);
    load_stage(1);

    int arow_off = (lane & 7) + ((lane >> 3) & 1) * 8;
    int acol_off = (lane >> 4) * 8;
    int brow_off = (lane & 7) + ((lane >> 4) << 3);
    int bcol_off = ((lane >> 3) & 1) * 8;

    const int NKB = D_ / 64;   // 16
    for (int kb = 0; kb < NKB; kb++) {
        CP_WAIT1();
        __syncthreads();
        uint32_t As_b = sbu + (uint32_t)((kb & 1) * 2 * GTILE);
        uint32_t Bs_b = As_b + GTILE;
#pragma unroll
        for (int kc = 0; kc < 4; kc++) {
            uint32_t a[2][4];
#pragma unroll
            for (int mi = 0; mi < 2; mi++) {
                uint4 r4 = ldm_x4(As_b + 2u * (uint32_t)(
                    (wm * 32 + mi * 16 + arow_off) * GP + kc * 16 + acol_off));
                a[mi][0] = r4.x; a[mi][1] = r4.y; a[mi][2] = r4.z; a[mi][3] = r4.w;
            }
#pragma unroll
            for (int p = 0; p < 4; p++) {
                uint4 bb = ldm_x4(Bs_b + 2u * (uint32_t)(
                    (wn * 64 + p * 16 + brow_off) * GP + kc * 16 + bcol_off));
#pragma unroll
                for (int mi = 0; mi < 2; mi++) {
                    mma_bf16(acc[mi][2 * p],     a[mi], bb.x, bb.y);
                    mma_bf16(acc[mi][2 * p + 1], a[mi], bb.z, bb.w);
                }
            }
        }
        __syncthreads();
        if (kb + 2 < NKB) load_stage(kb + 2);
        else CP_COMMIT();
    }

    // ------------------------- epilogue -------------------------
    int warp_n0 = n0 + wn * 64;
#pragma unroll
    for (int mi = 0; mi < 2; mi++) {
        int r0 = m0 + wm * 32 + mi * 16 + g;
        int b0 = r0 >> 11, l0m = r0 & (L_ - 1);

        if (mode == 0) {
            float* out = (float*)outv;
#pragma unroll
            for (int nj = 0; nj < 8; nj++) {
                int c0 = warp_n0 + nj * 8 + 2 * t;
                float2 bb = *(const float2*)&bias[c0];
                float2 ra = *(const float2*)&resid[(long)r0 * D_ + c0];
                float2 rb = *(const float2*)&resid[(long)(r0 + 8) * D_ + c0];
                *(float2*)&out[(long)r0 * D_ + c0] = make_float2(
                    acc[mi][nj][0] + bb.x + ra.x, acc[mi][nj][1] + bb.y + ra.y);
                *(float2*)&out[(long)(r0 + 8) * D_ + c0] = make_float2(
                    acc[mi][nj][2] + bb.x + rb.x, acc[mi][nj][3] + bb.y + rb.y);
            }
        } else if (mode == 1) {
            __nv_bfloat16* out = (__nv_bfloat16*)outv;
            int h = warp_n0 >> 6;
            const float* phb = phi + ((long)b0 * H_ + h) * L_;
            float sp0, cp0, sp1, cp1;
            sincosf(phb[l0m], &sp0, &cp0);
            sincosf(phb[l0m + 8], &sp1, &cp1);
            long base0 = (((long)(b0 * H_ + h)) * L_ + l0m) * HD_;
            long base1 = base0 + 8 * HD_;
#pragma unroll
            for (int nj = 0; nj < 4; nj++) {
                int d = nj * 8 + 2 * t;
                float2 bL = *(const float2*)&bias[warp_n0 + d];
                float2 bH = *(const float2*)&bias[warp_n0 + d + 32];
                float aL0 = acc[mi][nj][0] + bL.x, aL1 = acc[mi][nj][1] + bL.y;
                float aH0 = acc[mi][nj+4][0] + bH.x, aH1 = acc[mi][nj+4][1] + bH.y;
                *(uint32_t*)&out[base0 + d] = packbf(
                    (aL0 * cp0 - aH0 * sp0) * scale, (aL1 * cp0 - aH1 * sp0) * scale);
                *(uint32_t*)&out[base0 + d + 32] = packbf(
                    (aH0 * cp0 + aL0 * sp0) * scale, (aH1 * cp0 + aL1 * sp0) * scale);
                float cL0 = acc[mi][nj][2] + bL.x, cL1 = acc[mi][nj][3] + bL.y;
                float cH0 = acc[mi][nj+4][2] + bH.x, cH1 = acc[mi][nj+4][3] + bH.y;
                *(uint32_t*)&out[base1 + d] = packbf(
                    (cL0 * cp1 - cH0 * sp1) * scale, (cL1 * cp1 - cH1 * sp1) * scale);
                *(uint32_t*)&out[base1 + d + 32] = packbf(
                    (cH0 * cp1 + cL0 * sp1) * scale, (cH1 * cp1 + cL1 * sp1) * scale);
            }
        } else {   // mode 2: vT [b,h,d,l] bf16
            __nv_bfloat16* out = (__nv_bfloat16*)outv;
            int h = warp_n0 >> 6;
            long hb = ((long)(b0 * H_ + h)) * HD_;
#pragma unroll
            for (int nj = 0; nj < 8; nj++) {
                int d = nj * 8 + 2 * t;
                float2 bb = *(const float2*)&bias[warp_n0 + d];
                out[(hb + d    ) * L_ + l0m]     = __float2bfloat16(acc[mi][nj][0] + bb.x);
                out[(hb + d + 1) * L_ + l0m]     = __float2bfloat16(acc[mi][nj][1] + bb.y);
                out[(hb + d    ) * L_ + l0m + 8] = __float2bfloat16(acc[mi][nj][2] + bb.x);
                out[(hb + d + 1) * L_ + l0m + 8] = __float2bfloat16(acc[mi][nj][3] + bb.y);
            }
        }
    }
}

// ---------------------------------------------------------------------------
// Flash attention, bf16 m16n8k16 + ldmatrix, cp.async double-buffered K/V.
// Br=128, Bc=64, hd=64. 128 threads (4 warps), warp w owns rows w*32..w*32+31
// (two 16-row A-tiles). Q A-fragments reloaded from SMEM per ktile (keeps
// registers <= 168 for 3 CTAs/SM -> 12 warps/SM MUFU/tensor overlap).
// C=0 softmax (exact): no running max, row sums reduced once at the end.
// ---------------------------------------------------------------------------
#define QPITCH 72
#define FQS 0
#define FKS (128*QPITCH*2)               // 18432
#define FVS (FKS + 2*64*QPITCH*2)        // 36864
#define FMS (FVS + 2*64*QPITCH*2)        // 55296
#define FLASH_SMEM (FMS + 64*4)          // 55552 B

__global__ void __launch_bounds__(128, 3) flash_mma(
    const __nv_bfloat16* __restrict__ q, const __nv_bfloat16* __restrict__ k,
    const __nv_bfloat16* __restrict__ vT, const float* __restrict__ mask,
    __nv_bfloat16* __restrict__ ctx)
{
    extern __shared__ __align__(16) char fsm[];
    uint32_t sbu = smem_u32(fsm);
    float* ms = (float*)(fsm + FMS);

    int tid = threadIdx.x, lane = tid & 31, wid = tid >> 5;
    int g = lane >> 2, t = lane & 3;
    int bh = blockIdx.y;
    int b  = bh >> 4, h = bh & (H_ - 1);
    int l0 = blockIdx.x * 128;

    const __nv_bfloat16* qb  = q  + ((long)bh * L_ + l0) * HD_;
    const __nv_bfloat16* kb  = k  + (long)bh * L_ * HD_;
    const __nv_bfloat16* vtb = vT + (long)bh * HD_ * L_;

    auto load_kv = [&](int kt) {
        int st = kt & 1;
        uint32_t kbase = sbu + FKS + (uint32_t)(st * 64 * QPITCH * 2);
        uint32_t vbase = sbu + FVS + (uint32_t)(st * 64 * QPITCH * 2);
#pragma unroll
        for (int i = 0; i < 4; i++) {
            int idx = tid + i * 128;     // 0..511
            int r = idx >> 3, ch = idx & 7;
            uint32_t off = (uint32_t)(r * (QPITCH * 2) + ch * 16);
            CP_ASYNC16(kbase + off, kb + (long)(kt * 64 + r) * HD_ + ch * 8);
            CP_ASYNC16(vbase + off, vtb + (long)r * L_ + kt * 64 + ch * 8);
        }
        CP_COMMIT();
    };

    // Q tile: 128 rows x 8 chunks = 1024 chunks
    {
        uint32_t qbase = sbu + FQS;
#pragma unroll
        for (int i = 0; i < 8; i++) {
            int idx = tid + i * 128;
            int r = idx >> 3, ch = idx & 7;
            CP_ASYNC16(qbase + (uint32_t)(r * (QPITCH * 2) + ch * 16),
                       qb + (long)r * HD_ + ch * 8);
        }
        CP_COMMIT();
    }
    load_kv(0);
    CP_WAIT1();          // Q complete
    __syncthreads();

    int arow_off = (lane & 7) + ((lane >> 3) & 1) * 8;
    int acol_off = (lane >> 4) * 8;
    int brow_off = (lane & 7) + ((lane >> 4) << 3);
    int bcol_off = ((lane >> 3) & 1) * 8;

    float lp[2][2] = {{0.f, 0.f}, {0.f, 0.f}};   // per-thread row sums
    float o[2][8][4];
#pragma unroll
    for (int mi = 0; mi < 2; mi++)
#pragma unroll
        for (int nj = 0; nj < 8; nj++)
#pragma unroll
            for (int x = 0; x < 4; x++) o[mi][nj][x] = 0.f;

    const int NT = L_ / 64;
    for (int kt = 0; kt < NT; kt++) {
        __syncthreads();                 // all warps done with buffer (kt+1)&1
        if (tid < 64) ms[tid] = mask[(long)b * L_ + kt * 64 + tid];
        if (kt + 1 < NT) load_kv(kt + 1);
        else CP_COMMIT();
        CP_WAIT1();                      // tile kt landed
        __syncthreads();

        int st = kt & 1;
        uint32_t ks_base = sbu + FKS + (uint32_t)(st * 64 * QPITCH * 2);
        uint32_t vs_base = sbu + FVS + (uint32_t)(st * 64 * QPITCH * 2);

        // ---- S = Q K^T ----  (Q frags reloaded per kc; K frag feeds 2 MMAs)
        float s[2][8][4];
#pragma unroll
        for (int mi = 0; mi < 2; mi++)
#pragma unroll
            for (int nj = 0; nj < 8; nj++)
#pragma unroll
                for (int x = 0; x < 4; x++) s[mi][nj][x] = 0.f;
#pragma unroll
        for (int kc = 0; kc < 4; kc++) {
            uint32_t a[2][4];
#pragma unroll
            for (int mi = 0; mi < 2; mi++) {
                uint4 r4 = ldm_x4(sbu + FQS + 2u * (uint32_t)(
                    (wid * 32 + mi * 16 + arow_off) * QPITCH + kc * 16 + acol_off));
                a[mi][0] = r4.x; a[mi][1] = r4.y; a[mi][2] = r4.z; a[mi][3] = r4.w;
            }
#pragma unroll
            for (int p = 0; p < 4; p++) {
                uint4 bb = ldm_x4(ks_base + 2u * (uint32_t)(
                    (p * 16 + brow_off) * QPITCH + kc * 16 + bcol_off));
#pragma unroll
                for (int mi = 0; mi < 2; mi++) {
                    mma_bf16(s[mi][2 * p],     a[mi], bb.x, bb.y);
                    mma_bf16(s[mi][2 * p + 1], a[mi], bb.z, bb.w);
                }
            }
        }

        // ---- softmax numerator: exp(s + mask), accumulate row sums ----
        uint32_t pa[2][4][4];
#pragma unroll
        for (int mi = 0; mi < 2; mi++) {
#pragma unroll
            for (int nj = 0; nj < 8; nj++) {
                int c0 = nj * 8 + 2 * t;
                float mk0 = ms[c0], mk1 = ms[c0 + 1];
                s[mi][nj][0] = __expf(s[mi][nj][0] + mk0);
                s[mi][nj][1] = __expf(s[mi][nj][1] + mk1);
                s[mi][nj][2] = __expf(s[mi][nj][2] + mk0);
                s[mi][nj][3] = __expf(s[mi][nj][3] + mk1);
                lp[mi][0] += s[mi][nj][0] + s[mi][nj][1];
                lp[mi][1] += s[mi][nj][2] + s[mi][nj][3];
            }
#pragma unroll
            for (int kc = 0; kc < 4; kc++) {
                pa[mi][kc][0] = packbf(s[mi][2*kc][0],   s[mi][2*kc][1]);
                pa[mi][kc][1] = packbf(s[mi][2*kc][2],   s[mi][2*kc][3]);
                pa[mi][kc][2] = packbf(s[mi][2*kc+1][0], s[mi][2*kc+1][1]);
                pa[mi][kc][3] = packbf(s[mi][2*kc+1][2], s[mi][2*kc+1][3]);
            }
        }

        // ---- O += P V ----  (each V fragment feeds 2 mi MMAs)
#pragma unroll
        for (int kc = 0; kc < 4; kc++) {
#pragma unroll
            for (int p = 0; p < 4; p++) {
                uint4 bb = ldm_x4(vs_base + 2u * (uint32_t)(
                    (p * 16 + brow_off) * QPITCH + kc * 16 + bcol_off));
#pragma unroll
                for (int mi = 0; mi < 2; mi++) {
                    mma_bf16(o[mi][2 * p],     pa[mi][kc], bb.x, bb.y);
                    mma_bf16(o[mi][2 * p + 1], pa[mi][kc], bb.z, bb.w);
                }
            }
        }
    }

    // final row-sum reduction (once)
#pragma unroll
    for (int mi = 0; mi < 2; mi++) {
#pragma unroll
        for (int half = 0; half < 2; half++) {
            lp[mi][half] += __shfl_xor_sync(0xffffffffu, lp[mi][half], 1);
            lp[mi][half] += __shfl_xor_sync(0xffffffffu, lp[mi][half], 2);
        }
    }

    // epilogue: ctx[b, l, h, d] bf16
#pragma unroll
    for (int mi = 0; mi < 2; mi++) {
        float inv0 = 1.f / lp[mi][0], inv1 = 1.f / lp[mi][1];
        long row0 = (long)b * L_ + l0 + wid * 32 + mi * 16 + g;
        long row1 = row0 + 8;
#pragma unroll
        for (int nj = 0; nj < 8; nj++) {
            int c0 = h * HD_ + nj * 8 + 2 * t;
            *(uint32_t*)&ctx[row0 * D_ + c0] =
                packbf(o[mi][nj][0] * inv0, o[mi][nj][1] * inv0);
            *(uint32_t*)&ctx[row1 * D_ + c0] =
                packbf(o[mi][nj][2] * inv1, o[mi][nj][3] * inv1);
        }
    }
}

// ---------------------------------------------------------------------------
// In-place LayerNorm over last dim (1024).
// ---------------------------------------------------------------------------
__global__ void __launch_bounds__(256) ln_kernel(
    float* __restrict__ io, const float* __restrict__ gamma,
    const float* __restrict__ beta)
{
    __shared__ float ss[8], sq[8];
    __shared__ float s_mu, s_rs;
    int row = blockIdx.x, tid = threadIdx.x;
    float* p = io + (long)row * D_;
    float4 x = *(const float4*)&p[tid * 4];
    float s = x.x + x.y + x.z + x.w;
    float qq = x.x * x.x + x.y * x.y + x.z * x.z + x.w * x.w;
#pragma unroll
    for (int off = 16; off; off >>= 1) {
        s  += __shfl_xor_sync(0xffffffffu, s, off);
        qq += __shfl_xor_sync(0xffffffffu, qq, off);
    }
    int w = tid / 32;
    if ((tid & 31) == 0) { ss[w] = s; sq[w] = qq; }
    __syncthreads();
    if (tid == 0) {
        float S = 0.f, Q = 0.f;
#pragma unroll
        for (int i = 0; i < 8; i++) { S += ss[i]; Q += sq[i]; }
        float mu = S * (1.f / D_);
        float var = Q * (1.f / D_) - mu * mu;
        s_mu = mu;
        s_rs = rsqrtf(var + 1e-12f);
    }
    __syncthreads();
    float mu = s_mu, rs = s_rs;
    float4 gv = *(const float4*)&gamma[tid * 4];
    float4 be = *(const float4*)&beta[tid * 4];
    x.x = (x.x - mu) * rs * gv.x + be.x;
    x.y = (x.y - mu) * rs * gv.y + be.y;
    x.z = (x.z - mu) * rs * gv.z + be.z;
    x.w = (x.w - mu) * rs * gv.w + be.w;
    *(float4*)&p[tid * 4] = x;
}

// ---------------------------------------------------------------------------
extern "C" void kernel_launch(void* const* d_in, const int* in_sizes, int n_in,
                              void* d_out, int out_size)
{
    (void)in_sizes; (void)n_in; (void)out_size;
    const float* X    = (const float*)d_in[0];
    const float* mask = (const float*)d_in[1];
    const float* phi  = (const float*)d_in[2];
    const float* Wq   = (const float*)d_in[3];
    const float* bq   = (const float*)d_in[4];
    const float* Wk   = (const float*)d_in[5];
    const float* bk   = (const float*)d_in[6];
    const float* Wv   = (const float*)d_in[7];
    const float* bv   = (const float*)d_in[8];
    const float* Wo   = (const float*)d_in[9];
    const float* bo   = (const float*)d_in[10];
    const float* gamma= (const float*)d_in[11];
    const float* beta = (const float*)d_in[12];
    float* out = (float*)d_out;

    __nv_bfloat16 *xbf, *wq, *wk, *wv, *wo, *q, *k, *vT, *ctx;
    cudaGetSymbolAddress((void**)&xbf, g_xbf);
    cudaGetSymbolAddress((void**)&wq,  g_wq);
    cudaGetSymbolAddress((void**)&wk,  g_wk);
    cudaGetSymbolAddress((void**)&wv,  g_wv);
    cudaGetSymbolAddress((void**)&wo,  g_wo);
    cudaGetSymbolAddress((void**)&q,   g_q);
    cudaGetSymbolAddress((void**)&k,   g_k);
    cudaGetSymbolAddress((void**)&vT,  g_vT);
    cudaGetSymbolAddress((void**)&ctx, g_ctx);

    cudaFuncSetAttribute(gemm_bf16,
        cudaFuncAttributeMaxDynamicSharedMemorySize, GEMM_SMEM);
    cudaFuncSetAttribute(flash_mma,
        cudaFuncAttributeMaxDynamicSharedMemorySize, FLASH_SMEM);

    // fp32 -> bf16 conversions (X + 4 weights, single launch)
    cvt_all<<<(NX4 + 4*NW4) / 256, 256>>>(X, Wq, Wk, Wv, Wo,
                                          xbf, wq, wk, wv, wo);

    // fused QKV projection (gridDim.z = 3) with rotary / vT epilogues
    gemm_bf16<<<dim3(D_/128, M_/128, 3), 256, GEMM_SMEM>>>(
        xbf, wq, wk, wv, bq, bk, bv, nullptr, phi, q, k, vT, 1);

    // flash attention -> ctx bf16 [b,l,h,d]  (128 threads, 3 CTAs/SM)
    flash_mma<<<dim3(L_/128, B_*H_), 128, FLASH_SMEM>>>(q, k, vT, mask, ctx);

    // O projection + bias + residual(fp32 X) -> d_out
    gemm_bf16<<<dim3(D_/128, M_/128, 1), 256, GEMM_SMEM>>>(
        ctx, wo, nullptr, nullptr, bo, nullptr, nullptr, X, nullptr,
        out, nullptr, nullptr, 0);

    // in-place LayerNorm
    ln_kernel<<<M_, 256>>>(out, gamma, beta);
}

// round 13
// speedup vs baseline: 1.0468x; 1.0468x over previous
#include <cuda_runtime.h>
#include <cuda_bf16.h>
#include <cstdint>
#include <math.h>

// ---------------------------------------------------------------------------
// BehavioralRotaryAttentionV25: B=2, L=2048, D=1024, H=16, hd=64 (fp32 I/O)
// R13: R11 flash restored (2 CTA/SM, cached Q frags); cvt_all fusion kept.
// ---------------------------------------------------------------------------

#define B_ 2
#define L_ 2048
#define D_ 1024
#define H_ 16
#define HD_ 64
#define M_ (B_*L_)
#define BHLHD (B_*H_*L_*HD_)

__device__ __nv_bfloat16 g_xbf [M_*D_];   // X bf16 [M][D]
__device__ __nv_bfloat16 g_wq  [D_*D_];
__device__ __nv_bfloat16 g_wk  [D_*D_];
__device__ __nv_bfloat16 g_wv  [D_*D_];
__device__ __nv_bfloat16 g_wo  [D_*D_];
__device__ __nv_bfloat16 g_q   [BHLHD];   // [b,h,l,d] (rotary, scaled 1/8)
__device__ __nv_bfloat16 g_k   [BHLHD];   // [b,h,l,d] (rotary)
__device__ __nv_bfloat16 g_vT  [BHLHD];   // [b,h,d,l]
__device__ __nv_bfloat16 g_ctx [M_*D_];   // [b,l,h,d] == [M][D]

// ------------------------- helpers -----------------------------------------
__device__ __forceinline__ void mma_bf16(float c[4], const uint32_t a[4],
                                         uint32_t b0, uint32_t b1) {
    asm volatile(
        "mma.sync.aligned.m16n8k16.row.col.f32.bf16.bf16.f32 "
        "{%0,%1,%2,%3}, {%4,%5,%6,%7}, {%8,%9}, {%0,%1,%2,%3};"
        : "+f"(c[0]), "+f"(c[1]), "+f"(c[2]), "+f"(c[3])
        : "r"(a[0]), "r"(a[1]), "r"(a[2]), "r"(a[3]), "r"(b0), "r"(b1));
}
__device__ __forceinline__ uint4 ldm_x4(uint32_t addr) {
    uint4 r;
    asm volatile("ldmatrix.sync.aligned.m8n8.x4.shared.b16 {%0,%1,%2,%3}, [%4];"
        : "=r"(r.x), "=r"(r.y), "=r"(r.z), "=r"(r.w) : "r"(addr));
    return r;
}
__device__ __forceinline__ uint32_t packbf(float lo, float hi) {
    __nv_bfloat162 h = __floats2bfloat162_rn(lo, hi);
    return *(uint32_t*)&h;
}
__device__ __forceinline__ uint32_t smem_u32(const void* p) {
    uint32_t a;
    asm("{ .reg .u64 t; cvta.to.shared.u64 t, %1; cvt.u32.u64 %0, t; }"
        : "=r"(a) : "l"(p));
    return a;
}
#define CP_ASYNC16(saddr, gptr) \
    asm volatile("cp.async.cg.shared.global [%0], [%1], 16;" \
        :: "r"((uint32_t)(saddr)), "l"(gptr) : "memory")
#define CP_COMMIT() asm volatile("cp.async.commit_group;" ::: "memory")
#define CP_WAIT1()  asm volatile("cp.async.wait_group 1;" ::: "memory")

// ---------------------------------------------------------------------------
// fused fp32 -> bf16 convert: X (1M uint2) + 4 weights (256K uint2 each).
// ---------------------------------------------------------------------------
#define NX4 (M_*D_/4)        // 1048576
#define NW4 (D_*D_/4)        // 262144

__global__ void __launch_bounds__(256) cvt_all(
    const float* __restrict__ X,
    const float* __restrict__ w0, const float* __restrict__ w1,
    const float* __restrict__ w2, const float* __restrict__ w3,
    __nv_bfloat16* __restrict__ xo,
    __nv_bfloat16* __restrict__ o0, __nv_bfloat16* __restrict__ o1,
    __nv_bfloat16* __restrict__ o2, __nv_bfloat16* __restrict__ o3)
{
    int i = blockIdx.x * 256 + threadIdx.x;
    const float* in;
    __nv_bfloat16* out;
    int off;
    if (i < NX4) {
        in = X; out = xo; off = i;
    } else {
        int j = i - NX4;
        int w = j >> 18;           // / NW4
        off = j & (NW4 - 1);
        in  = (w == 0) ? w0 : (w == 1) ? w1 : (w == 2) ? w2 : w3;
        out = (w == 0) ? o0 : (w == 1) ? o1 : (w == 2) ? o2 : o3;
    }
    float4 x = ((const float4*)in)[off];
    ((uint2*)out)[off] = make_uint2(packbf(x.x, x.y), packbf(x.z, x.w));
}

// ---------------------------------------------------------------------------
// bf16 GEMM (unchanged): CTA 128x128, BK=64, double buffer.
// ---------------------------------------------------------------------------
#define GP 72
#define GTILE (128*GP*2)              // 18432 B per tile
#define GEMM_SMEM (2*2*GTILE)         // 73728 B

__global__ void __launch_bounds__(256, 2) gemm_bf16(
    const __nv_bfloat16* __restrict__ A,
    const __nv_bfloat16* __restrict__ W0, const __nv_bfloat16* __restrict__ W1,
    const __nv_bfloat16* __restrict__ W2,
    const float* __restrict__ b0v, const float* __restrict__ b1v,
    const float* __restrict__ b2v,
    const float* __restrict__ resid, const float* __restrict__ phi,
    void* __restrict__ out0, void* __restrict__ out1, void* __restrict__ out2,
    int qkv)
{
    extern __shared__ __align__(16) __nv_bfloat16 smem[];
    uint32_t sbu = smem_u32(smem);
    int tid = threadIdx.x, lane = tid & 31, wid = tid >> 5;
    int g = lane >> 2, t = lane & 3;
    int wm = wid >> 1, wn = wid & 1;
    int m0 = blockIdx.y * 128, n0 = blockIdx.x * 128;
    int z = blockIdx.z;

    const __nv_bfloat16* W = qkv ? ((z == 0) ? W0 : (z == 1) ? W1 : W2) : W0;
    const float* bias = qkv ? ((z == 0) ? b0v : (z == 1) ? b1v : b2v) : b0v;
    void* outv = qkv ? ((z == 0) ? out0 : (z == 1) ? out1 : out2) : out0;
    int mode = qkv ? ((z == 2) ? 2 : 1) : 0;
    float scale = (qkv && z == 0) ? 0.125f : 1.f;

    const __nv_bfloat16* Ab = A + (long)m0 * D_;
    const __nv_bfloat16* Wb = W + (long)n0 * D_;

    auto load_stage = [&](int kb) {
        int s = kb & 1;
        uint32_t abase = sbu + (uint32_t)(s * 2 * GTILE);
        uint32_t bbase = abase + GTILE;
        int k0 = kb * 64;
#pragma unroll
        for (int i = 0; i < 4; i++) {
            int idx = tid + i * 256;
            int row = idx >> 3, ch = idx & 7;
            uint32_t off = (uint32_t)(row * (GP * 2) + ch * 16);
            CP_ASYNC16(abase + off, Ab + (long)row * D_ + k0 + ch * 8);
            CP_ASYNC16(bbase + off, Wb + (long)row * D_ + k0 + ch * 8);
        }
        CP_COMMIT();
    };

    float acc[2][8][4];
#pragma unroll
    for (int mi = 0; mi < 2; mi++)
#pragma unroll
        for (int nj = 0; nj < 8; nj++)
#pragma unroll
            for (int x = 0; x < 4; x++) acc[mi][nj][x] = 0.f;

    load_stage(0);
    load_stage(1);

    int arow_off = (lane & 7) + ((lane >> 3) & 1) * 8;
    int acol_off = (lane >> 4) * 8;
    int brow_off = (lane & 7) + ((lane >> 4) << 3);
    int bcol_off = ((lane >> 3) & 1) * 8;

    const int NKB = D_ / 64;   // 16
    for (int kb = 0; kb < NKB; kb++) {
        CP_WAIT1();
        __syncthreads();
        uint32_t As_b = sbu + (uint32_t)((kb & 1) * 2 * GTILE);
        uint32_t Bs_b = As_b + GTILE;
#pragma unroll
        for (int kc = 0; kc < 4; kc++) {
            uint32_t a[2][4];
#pragma unroll
            for (int mi = 0; mi < 2; mi++) {
                uint4 r4 = ldm_x4(As_b + 2u * (uint32_t)(
                    (wm * 32 + mi * 16 + arow_off) * GP + kc * 16 + acol_off));
                a[mi][0] = r4.x; a[mi][1] = r4.y; a[mi][2] = r4.z; a[mi][3] = r4.w;
            }
#pragma unroll
            for (int p = 0; p < 4; p++) {
                uint4 bb = ldm_x4(Bs_b + 2u * (uint32_t)(
                    (wn * 64 + p * 16 + brow_off) * GP + kc * 16 + bcol_off));
#pragma unroll
                for (int mi = 0; mi < 2; mi++) {
                    mma_bf16(acc[mi][2 * p],     a[mi], bb.x, bb.y);
                    mma_bf16(acc[mi][2 * p + 1], a[mi], bb.z, bb.w);
                }
            }
        }
        __syncthreads();
        if (kb + 2 < NKB) load_stage(kb + 2);
        else CP_COMMIT();
    }

    // ------------------------- epilogue -------------------------
    int warp_n0 = n0 + wn * 64;
#pragma unroll
    for (int mi = 0; mi < 2; mi++) {
        int r0 = m0 + wm * 32 + mi * 16 + g;
        int b0 = r0 >> 11, l0m = r0 & (L_ - 1);

        if (mode == 0) {
            float* out = (float*)outv;
#pragma unroll
            for (int nj = 0; nj < 8; nj++) {
                int c0 = warp_n0 + nj * 8 + 2 * t;
                float2 bb = *(const float2*)&bias[c0];
                float2 ra = *(const float2*)&resid[(long)r0 * D_ + c0];
                float2 rb = *(const float2*)&resid[(long)(r0 + 8) * D_ + c0];
                *(float2*)&out[(long)r0 * D_ + c0] = make_float2(
                    acc[mi][nj][0] + bb.x + ra.x, acc[mi][nj][1] + bb.y + ra.y);
                *(float2*)&out[(long)(r0 + 8) * D_ + c0] = make_float2(
                    acc[mi][nj][2] + bb.x + rb.x, acc[mi][nj][3] + bb.y + rb.y);
            }
        } else if (mode == 1) {
            __nv_bfloat16* out = (__nv_bfloat16*)outv;
            int h = warp_n0 >> 6;
            const float* phb = phi + ((long)b0 * H_ + h) * L_;
            float sp0, cp0, sp1, cp1;
            sincosf(phb[l0m], &sp0, &cp0);
            sincosf(phb[l0m + 8], &sp1, &cp1);
            long base0 = (((long)(b0 * H_ + h)) * L_ + l0m) * HD_;
            long base1 = base0 + 8 * HD_;
#pragma unroll
            for (int nj = 0; nj < 4; nj++) {
                int d = nj * 8 + 2 * t;
                float2 bL = *(const float2*)&bias[warp_n0 + d];
                float2 bH = *(const float2*)&bias[warp_n0 + d + 32];
                float aL0 = acc[mi][nj][0] + bL.x, aL1 = acc[mi][nj][1] + bL.y;
                float aH0 = acc[mi][nj+4][0] + bH.x, aH1 = acc[mi][nj+4][1] + bH.y;
                *(uint32_t*)&out[base0 + d] = packbf(
                    (aL0 * cp0 - aH0 * sp0) * scale, (aL1 * cp0 - aH1 * sp0) * scale);
                *(uint32_t*)&out[base0 + d + 32] = packbf(
                    (aH0 * cp0 + aL0 * sp0) * scale, (aH1 * cp0 + aL1 * sp0) * scale);
                float cL0 = acc[mi][nj][2] + bL.x, cL1 = acc[mi][nj][3] + bL.y;
                float cH0 = acc[mi][nj+4][2] + bH.x, cH1 = acc[mi][nj+4][3] + bH.y;
                *(uint32_t*)&out[base1 + d] = packbf(
                    (cL0 * cp1 - cH0 * sp1) * scale, (cL1 * cp1 - cH1 * sp1) * scale);
                *(uint32_t*)&out[base1 + d + 32] = packbf(
                    (cH0 * cp1 + cL0 * sp1) * scale, (cH1 * cp1 + cL1 * sp1) * scale);
            }
        } else {   // mode 2: vT [b,h,d,l] bf16
            __nv_bfloat16* out = (__nv_bfloat16*)outv;
            int h = warp_n0 >> 6;
            long hb = ((long)(b0 * H_ + h)) * HD_;
#pragma unroll
            for (int nj = 0; nj < 8; nj++) {
                int d = nj * 8 + 2 * t;
                float2 bb = *(const float2*)&bias[warp_n0 + d];
                out[(hb + d    ) * L_ + l0m]     = __float2bfloat16(acc[mi][nj][0] + bb.x);
                out[(hb + d + 1) * L_ + l0m]     = __float2bfloat16(acc[mi][nj][1] + bb.y);
                out[(hb + d    ) * L_ + l0m + 8] = __float2bfloat16(acc[mi][nj][2] + bb.x);
                out[(hb + d + 1) * L_ + l0m + 8] = __float2bfloat16(acc[mi][nj][3] + bb.y);
            }
        }
    }
}

// ---------------------------------------------------------------------------
// Flash attention (R11 config restored): bf16 m16n8k16 + ldmatrix, cp.async
// double-buffered K/V. Br=128, Bc=64, hd=64. 128 threads (4 warps), warp w
// owns rows w*32..w*32+31 (two 16-row A-tiles; B-fragment reuse 2x). Cached
// Q A-fragments (2 CTAs/SM, ~228 regs, no spills). C=0 softmax.
// ---------------------------------------------------------------------------
#define QPITCH 72
#define FQS 0
#define FKS (128*QPITCH*2)               // 18432
#define FVS (FKS + 2*64*QPITCH*2)        // 36864
#define FMS (FVS + 2*64*QPITCH*2)        // 55296
#define FLASH_SMEM (FMS + 64*4)          // 55552 B

__global__ void __launch_bounds__(128, 2) flash_mma(
    const __nv_bfloat16* __restrict__ q, const __nv_bfloat16* __restrict__ k,
    const __nv_bfloat16* __restrict__ vT, const float* __restrict__ mask,
    __nv_bfloat16* __restrict__ ctx)
{
    extern __shared__ __align__(16) char fsm[];
    uint32_t sbu = smem_u32(fsm);
    float* ms = (float*)(fsm + FMS);

    int tid = threadIdx.x, lane = tid & 31, wid = tid >> 5;
    int g = lane >> 2, t = lane & 3;
    int bh = blockIdx.y;
    int b  = bh >> 4, h = bh & (H_ - 1);
    int l0 = blockIdx.x * 128;

    const __nv_bfloat16* qb  = q  + ((long)bh * L_ + l0) * HD_;
    const __nv_bfloat16* kb  = k  + (long)bh * L_ * HD_;
    const __nv_bfloat16* vtb = vT + (long)bh * HD_ * L_;

    auto load_kv = [&](int kt) {
        int st = kt & 1;
        uint32_t kbase = sbu + FKS + (uint32_t)(st * 64 * QPITCH * 2);
        uint32_t vbase = sbu + FVS + (uint32_t)(st * 64 * QPITCH * 2);
#pragma unroll
        for (int i = 0; i < 4; i++) {
            int idx = tid + i * 128;     // 0..511
            int r = idx >> 3, ch = idx & 7;
            uint32_t off = (uint32_t)(r * (QPITCH * 2) + ch * 16);
            CP_ASYNC16(kbase + off, kb + (long)(kt * 64 + r) * HD_ + ch * 8);
            CP_ASYNC16(vbase + off, vtb + (long)r * L_ + kt * 64 + ch * 8);
        }
        CP_COMMIT();
    };

    // Q tile: 128 rows x 8 chunks = 1024 chunks
    {
        uint32_t qbase = sbu + FQS;
#pragma unroll
        for (int i = 0; i < 8; i++) {
            int idx = tid + i * 128;
            int r = idx >> 3, ch = idx & 7;
            CP_ASYNC16(qbase + (uint32_t)(r * (QPITCH * 2) + ch * 16),
                       qb + (long)r * HD_ + ch * 8);
        }
        CP_COMMIT();
    }
    load_kv(0);
    CP_WAIT1();          // Q complete
    __syncthreads();

    // hoist Q A-fragments: two 16-row tiles per warp
    uint32_t aq[2][4][4];
    {
        int arow_off = (lane & 7) + ((lane >> 3) & 1) * 8;
        int acol = (lane >> 4) * 8;
#pragma unroll
        for (int mi = 0; mi < 2; mi++) {
            int arow = wid * 32 + mi * 16 + arow_off;
#pragma unroll
            for (int kc = 0; kc < 4; kc++) {
                uint4 r4 = ldm_x4(sbu + FQS +
                    2u * (uint32_t)(arow * QPITCH + kc * 16 + acol));
                aq[mi][kc][0] = r4.x; aq[mi][kc][1] = r4.y;
                aq[mi][kc][2] = r4.z; aq[mi][kc][3] = r4.w;
            }
        }
    }

    float lp[2][2] = {{0.f, 0.f}, {0.f, 0.f}};   // per-thread row sums
    float o[2][8][4];
#pragma unroll
    for (int mi = 0; mi < 2; mi++)
#pragma unroll
        for (int nj = 0; nj < 8; nj++)
#pragma unroll
            for (int x = 0; x < 4; x++) o[mi][nj][x] = 0.f;

    int brow_off = (lane & 7) + ((lane >> 4) << 3);
    int bcol_off = ((lane >> 3) & 1) * 8;

    const int NT = L_ / 64;
    for (int kt = 0; kt < NT; kt++) {
        __syncthreads();                 // all warps done with buffer (kt+1)&1
        if (tid < 64) ms[tid] = mask[(long)b * L_ + kt * 64 + tid];
        if (kt + 1 < NT) load_kv(kt + 1);
        else CP_COMMIT();
        CP_WAIT1();                      // tile kt landed
        __syncthreads();

        int st = kt & 1;
        uint32_t ks_base = sbu + FKS + (uint32_t)(st * 64 * QPITCH * 2);
        uint32_t vs_base = sbu + FVS + (uint32_t)(st * 64 * QPITCH * 2);

        // ---- S = Q K^T ----  (each K fragment feeds 2 mi MMAs)
        float s[2][8][4];
#pragma unroll
        for (int mi = 0; mi < 2; mi++)
#pragma unroll
            for (int nj = 0; nj < 8; nj++)
#pragma unroll
                for (int x = 0; x < 4; x++) s[mi][nj][x] = 0.f;
#pragma unroll
        for (int kc = 0; kc < 4; kc++) {
#pragma unroll
            for (int p = 0; p < 4; p++) {
                uint4 bb = ldm_x4(ks_base + 2u * (uint32_t)(
                    (p * 16 + brow_off) * QPITCH + kc * 16 + bcol_off));
#pragma unroll
                for (int mi = 0; mi < 2; mi++) {
                    mma_bf16(s[mi][2 * p],     aq[mi][kc], bb.x, bb.y);
                    mma_bf16(s[mi][2 * p + 1], aq[mi][kc], bb.z, bb.w);
                }
            }
        }

        // ---- softmax numerator: exp(s + mask), accumulate row sums ----
        uint32_t pa[2][4][4];
#pragma unroll
        for (int mi = 0; mi < 2; mi++) {
#pragma unroll
            for (int nj = 0; nj < 8; nj++) {
                int c0 = nj * 8 + 2 * t;
                float mk0 = ms[c0], mk1 = ms[c0 + 1];
                s[mi][nj][0] = __expf(s[mi][nj][0] + mk0);
                s[mi][nj][1] = __expf(s[mi][nj][1] + mk1);
                s[mi][nj][2] = __expf(s[mi][nj][2] + mk0);
                s[mi][nj][3] = __expf(s[mi][nj][3] + mk1);
                lp[mi][0] += s[mi][nj][0] + s[mi][nj][1];
                lp[mi][1] += s[mi][nj][2] + s[mi][nj][3];
            }
#pragma unroll
            for (int kc = 0; kc < 4; kc++) {
                pa[mi][kc][0] = packbf(s[mi][2*kc][0],   s[mi][2*kc][1]);
                pa[mi][kc][1] = packbf(s[mi][2*kc][2],   s[mi][2*kc][3]);
                pa[mi][kc][2] = packbf(s[mi][2*kc+1][0], s[mi][2*kc+1][1]);
                pa[mi][kc][3] = packbf(s[mi][2*kc+1][2], s[mi][2*kc+1][3]);
            }
        }

        // ---- O += P V ----  (each V fragment feeds 2 mi MMAs)
#pragma unroll
        for (int kc = 0; kc < 4; kc++) {
#pragma unroll
            for (int p = 0; p < 4; p++) {
                uint4 bb = ldm_x4(vs_base + 2u * (uint32_t)(
                    (p * 16 + brow_off) * QPITCH + kc * 16 + bcol_off));
#pragma unroll
                for (int mi = 0; mi < 2; mi++) {
                    mma_bf16(o[mi][2 * p],     pa[mi][kc], bb.x, bb.y);
                    mma_bf16(o[mi][2 * p + 1], pa[mi][kc], bb.z, bb.w);
                }
            }
        }
    }

    // final row-sum reduction (once)
#pragma unroll
    for (int mi = 0; mi < 2; mi++) {
#pragma unroll
        for (int half = 0; half < 2; half++) {
            lp[mi][half] += __shfl_xor_sync(0xffffffffu, lp[mi][half], 1);
            lp[mi][half] += __shfl_xor_sync(0xffffffffu, lp[mi][half], 2);
        }
    }

    // epilogue: ctx[b, l, h, d] bf16
#pragma unroll
    for (int mi = 0; mi < 2; mi++) {
        float inv0 = 1.f / lp[mi][0], inv1 = 1.f / lp[mi][1];
        long row0 = (long)b * L_ + l0 + wid * 32 + mi * 16 + g;
        long row1 = row0 + 8;
#pragma unroll
        for (int nj = 0; nj < 8; nj++) {
            int c0 = h * HD_ + nj * 8 + 2 * t;
            *(uint32_t*)&ctx[row0 * D_ + c0] =
                packbf(o[mi][nj][0] * inv0, o[mi][nj][1] * inv0);
            *(uint32_t*)&ctx[row1 * D_ + c0] =
                packbf(o[mi][nj][2] * inv1, o[mi][nj][3] * inv1);
        }
    }
}

// ---------------------------------------------------------------------------
// In-place LayerNorm over last dim (1024).
// ---------------------------------------------------------------------------
__global__ void __launch_bounds__(256) ln_kernel(
    float* __restrict__ io, const float* __restrict__ gamma,
    const float* __restrict__ beta)
{
    __shared__ float ss[8], sq[8];
    __shared__ float s_mu, s_rs;
    int row = blockIdx.x, tid = threadIdx.x;
    float* p = io + (long)row * D_;
    float4 x = *(const float4*)&p[tid * 4];
    float s = x.x + x.y + x.z + x.w;
    float qq = x.x * x.x + x.y * x.y + x.z * x.z + x.w * x.w;
#pragma unroll
    for (int off = 16; off; off >>= 1) {
        s  += __shfl_xor_sync(0xffffffffu, s, off);
        qq += __shfl_xor_sync(0xffffffffu, qq, off);
    }
    int w = tid / 32;
    if ((tid & 31) == 0) { ss[w] = s; sq[w] = qq; }
    __syncthreads();
    if (tid == 0) {
        float S = 0.f, Q = 0.f;
#pragma unroll
        for (int i = 0; i < 8; i++) { S += ss[i]; Q += sq[i]; }
        float mu = S * (1.f / D_);
        float var = Q * (1.f / D_) - mu * mu;
        s_mu = mu;
        s_rs = rsqrtf(var + 1e-12f);
    }
    __syncthreads();
    float mu = s_mu, rs = s_rs;
    float4 gv = *(const float4*)&gamma[tid * 4];
    float4 be = *(const float4*)&beta[tid * 4];
    x.x = (x.x - mu) * rs * gv.x + be.x;
    x.y = (x.y - mu) * rs * gv.y + be.y;
    x.z = (x.z - mu) * rs * gv.z + be.z;
    x.w = (x.w - mu) * rs * gv.w + be.w;
    *(float4*)&p[tid * 4] = x;
}

// ---------------------------------------------------------------------------
extern "C" void kernel_launch(void* const* d_in, const int* in_sizes, int n_in,
                              void* d_out, int out_size)
{
    (void)in_sizes; (void)n_in; (void)out_size;
    const float* X    = (const float*)d_in[0];
    const float* mask = (const float*)d_in[1];
    const float* phi  = (const float*)d_in[2];
    const float* Wq   = (const float*)d_in[3];
    const float* bq   = (const float*)d_in[4];
    const float* Wk   = (const float*)d_in[5];
    const float* bk   = (const float*)d_in[6];
    const float* Wv   = (const float*)d_in[7];
    const float* bv   = (const float*)d_in[8];
    const float* Wo   = (const float*)d_in[9];
    const float* bo   = (const float*)d_in[10];
    const float* gamma= (const float*)d_in[11];
    const float* beta = (const float*)d_in[12];
    float* out = (float*)d_out;

    __nv_bfloat16 *xbf, *wq, *wk, *wv, *wo, *q, *k, *vT, *ctx;
    cudaGetSymbolAddress((void**)&xbf, g_xbf);
    cudaGetSymbolAddress((void**)&wq,  g_wq);
    cudaGetSymbolAddress((void**)&wk,  g_wk);
    cudaGetSymbolAddress((void**)&wv,  g_wv);
    cudaGetSymbolAddress((void**)&wo,  g_wo);
    cudaGetSymbolAddress((void**)&q,   g_q);
    cudaGetSymbolAddress((void**)&k,   g_k);
    cudaGetSymbolAddress((void**)&vT,  g_vT);
    cudaGetSymbolAddress((void**)&ctx, g_ctx);

    cudaFuncSetAttribute(gemm_bf16,
        cudaFuncAttributeMaxDynamicSharedMemorySize, GEMM_SMEM);
    cudaFuncSetAttribute(flash_mma,
        cudaFuncAttributeMaxDynamicSharedMemorySize, FLASH_SMEM);

    // fp32 -> bf16 conversions (X + 4 weights, single launch)
    cvt_all<<<(NX4 + 4*NW4) / 256, 256>>>(X, Wq, Wk, Wv, Wo,
                                          xbf, wq, wk, wv, wo);

    // fused QKV projection (gridDim.z = 3) with rotary / vT epilogues
    gemm_bf16<<<dim3(D_/128, M_/128, 3), 256, GEMM_SMEM>>>(
        xbf, wq, wk, wv, bq, bk, bv, nullptr, phi, q, k, vT, 1);

    // flash attention -> ctx bf16 [b,l,h,d]  (128 threads, 2 CTAs/SM)
    flash_mma<<<dim3(L_/128, B_*H_), 128, FLASH_SMEM>>>(q, k, vT, mask, ctx);

    // O projection + bias + residual(fp32 X) -> d_out
    gemm_bf16<<<dim3(D_/128, M_/128, 1), 256, GEMM_SMEM>>>(
        ctx, wo, nullptr, nullptr, bo, nullptr, nullptr, X, nullptr,
        out, nullptr, nullptr, 0);

    // in-place LayerNorm
    ln_kernel<<<M_, 256>>>(out, gamma, beta);
}

// round 16
// speedup vs baseline: 1.0953x; 1.0464x over previous
#include <cuda_runtime.h>
#include <cuda_bf16.h>
#include <cstdint>
#include <math.h>

// ---------------------------------------------------------------------------
// BehavioralRotaryAttentionV25: B=2, L=2048, D=1024, H=16, hd=64 (fp32 I/O)
// R16: R13 baseline (2-stage gemm) + ex2/log2e flash delta only.
// ---------------------------------------------------------------------------

#define B_ 2
#define L_ 2048
#define D_ 1024
#define H_ 16
#define HD_ 64
#define M_ (B_*L_)
#define BHLHD (B_*H_*L_*HD_)
#define LOG2E 1.44269504f

__device__ __nv_bfloat16 g_xbf [M_*D_];   // X bf16 [M][D]
__device__ __nv_bfloat16 g_wq  [D_*D_];
__device__ __nv_bfloat16 g_wk  [D_*D_];
__device__ __nv_bfloat16 g_wv  [D_*D_];
__device__ __nv_bfloat16 g_wo  [D_*D_];
__device__ __nv_bfloat16 g_q   [BHLHD];   // [b,h,l,d] (rotary, scaled log2e/8)
__device__ __nv_bfloat16 g_k   [BHLHD];   // [b,h,l,d] (rotary)
__device__ __nv_bfloat16 g_vT  [BHLHD];   // [b,h,d,l]
__device__ __nv_bfloat16 g_ctx [M_*D_];   // [b,l,h,d] == [M][D]

// ------------------------- helpers -----------------------------------------
__device__ __forceinline__ void mma_bf16(float c[4], const uint32_t a[4],
                                         uint32_t b0, uint32_t b1) {
    asm volatile(
        "mma.sync.aligned.m16n8k16.row.col.f32.bf16.bf16.f32 "
        "{%0,%1,%2,%3}, {%4,%5,%6,%7}, {%8,%9}, {%0,%1,%2,%3};"
        : "+f"(c[0]), "+f"(c[1]), "+f"(c[2]), "+f"(c[3])
        : "r"(a[0]), "r"(a[1]), "r"(a[2]), "r"(a[3]), "r"(b0), "r"(b1));
}
__device__ __forceinline__ uint4 ldm_x4(uint32_t addr) {
    uint4 r;
    asm volatile("ldmatrix.sync.aligned.m8n8.x4.shared.b16 {%0,%1,%2,%3}, [%4];"
        : "=r"(r.x), "=r"(r.y), "=r"(r.z), "=r"(r.w) : "r"(addr));
    return r;
}
__device__ __forceinline__ uint32_t packbf(float lo, float hi) {
    __nv_bfloat162 h = __floats2bfloat162_rn(lo, hi);
    return *(uint32_t*)&h;
}
__device__ __forceinline__ float ex2f(float x) {
    float r;
    asm("ex2.approx.f32 %0, %1;" : "=f"(r) : "f"(x));
    return r;
}
__device__ __forceinline__ uint32_t smem_u32(const void* p) {
    uint32_t a;
    asm("{ .reg .u64 t; cvta.to.shared.u64 t, %1; cvt.u32.u64 %0, t; }"
        : "=r"(a) : "l"(p));
    return a;
}
#define CP_ASYNC16(saddr, gptr) \
    asm volatile("cp.async.cg.shared.global [%0], [%1], 16;" \
        :: "r"((uint32_t)(saddr)), "l"(gptr) : "memory")
#define CP_COMMIT() asm volatile("cp.async.commit_group;" ::: "memory")
#define CP_WAIT1()  asm volatile("cp.async.wait_group 1;" ::: "memory")

// ---------------------------------------------------------------------------
// fused fp32 -> bf16 convert: X (1M uint2) + 4 weights (256K uint2 each).
// ---------------------------------------------------------------------------
#define NX4 (M_*D_/4)        // 1048576
#define NW4 (D_*D_/4)        // 262144

__global__ void __launch_bounds__(256) cvt_all(
    const float* __restrict__ X,
    const float* __restrict__ w0, const float* __restrict__ w1,
    const float* __restrict__ w2, const float* __restrict__ w3,
    __nv_bfloat16* __restrict__ xo,
    __nv_bfloat16* __restrict__ o0, __nv_bfloat16* __restrict__ o1,
    __nv_bfloat16* __restrict__ o2, __nv_bfloat16* __restrict__ o3)
{
    int i = blockIdx.x * 256 + threadIdx.x;
    const float* in;
    __nv_bfloat16* out;
    int off;
    if (i < NX4) {
        in = X; out = xo; off = i;
    } else {
        int j = i - NX4;
        int w = j >> 18;           // / NW4
        off = j & (NW4 - 1);
        in  = (w == 0) ? w0 : (w == 1) ? w1 : (w == 2) ? w2 : w3;
        out = (w == 0) ? o0 : (w == 1) ? o1 : (w == 2) ? o2 : o3;
    }
    float4 x = ((const float4*)in)[off];
    ((uint2*)out)[off] = make_uint2(packbf(x.x, x.y), packbf(x.z, x.w));
}

// ---------------------------------------------------------------------------
// bf16 GEMM (R13 proven config): CTA 128x128, BK=64, 2-stage double buffer.
// 8 warps: wm (4) x wn (2); warp tile 32m x 64n (head-aligned).
// qkv != 0: gridDim.z = 3 -> {Wq->q rotary*scale, Wk->k rotary, Wv->vT}.
// qkv == 0: mode 0 (fp32 out + resid).
// ---------------------------------------------------------------------------
#define GP 72
#define GTILE (128*GP*2)              // 18432 B per tile
#define GEMM_SMEM (2*2*GTILE)         // 73728 B

__global__ void __launch_bounds__(256, 2) gemm_bf16(
    const __nv_bfloat16* __restrict__ A,
    const __nv_bfloat16* __restrict__ W0, const __nv_bfloat16* __restrict__ W1,
    const __nv_bfloat16* __restrict__ W2,
    const float* __restrict__ b0v, const float* __restrict__ b1v,
    const float* __restrict__ b2v,
    const float* __restrict__ resid, const float* __restrict__ phi,
    void* __restrict__ out0, void* __restrict__ out1, void* __restrict__ out2,
    int qkv)
{
    extern __shared__ __align__(16) __nv_bfloat16 smem[];
    uint32_t sbu = smem_u32(smem);
    int tid = threadIdx.x, lane = tid & 31, wid = tid >> 5;
    int g = lane >> 2, t = lane & 3;
    int wm = wid >> 1, wn = wid & 1;
    int m0 = blockIdx.y * 128, n0 = blockIdx.x * 128;
    int z = blockIdx.z;

    const __nv_bfloat16* W = qkv ? ((z == 0) ? W0 : (z == 1) ? W1 : W2) : W0;
    const float* bias = qkv ? ((z == 0) ? b0v : (z == 1) ? b1v : b2v) : b0v;
    void* outv = qkv ? ((z == 0) ? out0 : (z == 1) ? out1 : out2) : out0;
    int mode = qkv ? ((z == 2) ? 2 : 1) : 0;
    float scale = (qkv && z == 0) ? (0.125f * LOG2E) : 1.f;

    const __nv_bfloat16* Ab = A + (long)m0 * D_;
    const __nv_bfloat16* Wb = W + (long)n0 * D_;

    auto load_stage = [&](int kb) {
        int s = kb & 1;
        uint32_t abase = sbu + (uint32_t)(s * 2 * GTILE);
        uint32_t bbase = abase + GTILE;
        int k0 = kb * 64;
#pragma unroll
        for (int i = 0; i < 4; i++) {
            int idx = tid + i * 256;
            int row = idx >> 3, ch = idx & 7;
            uint32_t off = (uint32_t)(row * (GP * 2) + ch * 16);
            CP_ASYNC16(abase + off, Ab + (long)row * D_ + k0 + ch * 8);
            CP_ASYNC16(bbase + off, Wb + (long)row * D_ + k0 + ch * 8);
        }
        CP_COMMIT();
    };

    float acc[2][8][4];
#pragma unroll
    for (int mi = 0; mi < 2; mi++)
#pragma unroll
        for (int nj = 0; nj < 8; nj++)
#pragma unroll
            for (int x = 0; x < 4; x++) acc[mi][nj][x] = 0.f;

    load_stage(0);
    load_stage(1);

    int arow_off = (lane & 7) + ((lane >> 3) & 1) * 8;
    int acol_off = (lane >> 4) * 8;
    int brow_off = (lane & 7) + ((lane >> 4) << 3);
    int bcol_off = ((lane >> 3) & 1) * 8;

    const int NKB = D_ / 64;   // 16
    for (int kb = 0; kb < NKB; kb++) {
        CP_WAIT1();
        __syncthreads();
        uint32_t As_b = sbu + (uint32_t)((kb & 1) * 2 * GTILE);
        uint32_t Bs_b = As_b + GTILE;
#pragma unroll
        for (int kc = 0; kc < 4; kc++) {
            uint32_t a[2][4];
#pragma unroll
            for (int mi = 0; mi < 2; mi++) {
                uint4 r4 = ldm_x4(As_b + 2u * (uint32_t)(
                    (wm * 32 + mi * 16 + arow_off) * GP + kc * 16 + acol_off));
                a[mi][0] = r4.x; a[mi][1] = r4.y; a[mi][2] = r4.z; a[mi][3] = r4.w;
            }
#pragma unroll
            for (int p = 0; p < 4; p++) {
                uint4 bb = ldm_x4(Bs_b + 2u * (uint32_t)(
                    (wn * 64 + p * 16 + brow_off) * GP + kc * 16 + bcol_off));
#pragma unroll
                for (int mi = 0; mi < 2; mi++) {
                    mma_bf16(acc[mi][2 * p],     a[mi], bb.x, bb.y);
                    mma_bf16(acc[mi][2 * p + 1], a[mi], bb.z, bb.w);
                }
            }
        }
        __syncthreads();
        if (kb + 2 < NKB) load_stage(kb + 2);
        else CP_COMMIT();
    }

    // ------------------------- epilogue -------------------------
    int warp_n0 = n0 + wn * 64;
#pragma unroll
    for (int mi = 0; mi < 2; mi++) {
        int r0 = m0 + wm * 32 + mi * 16 + g;
        int b0 = r0 >> 11, l0m = r0 & (L_ - 1);

        if (mode == 0) {
            float* out = (float*)outv;
#pragma unroll
            for (int nj = 0; nj < 8; nj++) {
                int c0 = warp_n0 + nj * 8 + 2 * t;
                float2 bb = *(const float2*)&bias[c0];
                float2 ra = *(const float2*)&resid[(long)r0 * D_ + c0];
                float2 rb = *(const float2*)&resid[(long)(r0 + 8) * D_ + c0];
                *(float2*)&out[(long)r0 * D_ + c0] = make_float2(
                    acc[mi][nj][0] + bb.x + ra.x, acc[mi][nj][1] + bb.y + ra.y);
                *(float2*)&out[(long)(r0 + 8) * D_ + c0] = make_float2(
                    acc[mi][nj][2] + bb.x + rb.x, acc[mi][nj][3] + bb.y + rb.y);
            }
        } else if (mode == 1) {
            __nv_bfloat16* out = (__nv_bfloat16*)outv;
            int h = warp_n0 >> 6;
            const float* phb = phi + ((long)b0 * H_ + h) * L_;
            float sp0, cp0, sp1, cp1;
            sincosf(phb[l0m], &sp0, &cp0);
            sincosf(phb[l0m + 8], &sp1, &cp1);
            long base0 = (((long)(b0 * H_ + h)) * L_ + l0m) * HD_;
            long base1 = base0 + 8 * HD_;
#pragma unroll
            for (int nj = 0; nj < 4; nj++) {
                int d = nj * 8 + 2 * t;
                float2 bL = *(const float2*)&bias[warp_n0 + d];
                float2 bH = *(const float2*)&bias[warp_n0 + d + 32];
                float aL0 = acc[mi][nj][0] + bL.x, aL1 = acc[mi][nj][1] + bL.y;
                float aH0 = acc[mi][nj+4][0] + bH.x, aH1 = acc[mi][nj+4][1] + bH.y;
                *(uint32_t*)&out[base0 + d] = packbf(
                    (aL0 * cp0 - aH0 * sp0) * scale, (aL1 * cp0 - aH1 * sp0) * scale);
                *(uint32_t*)&out[base0 + d + 32] = packbf(
                    (aH0 * cp0 + aL0 * sp0) * scale, (aH1 * cp0 + aL1 * sp0) * scale);
                float cL0 = acc[mi][nj][2] + bL.x, cL1 = acc[mi][nj][3] + bL.y;
                float cH0 = acc[mi][nj+4][2] + bH.x, cH1 = acc[mi][nj+4][3] + bH.y;
                *(uint32_t*)&out[base1 + d] = packbf(
                    (cL0 * cp1 - cH0 * sp1) * scale, (cL1 * cp1 - cH1 * sp1) * scale);
                *(uint32_t*)&out[base1 + d + 32] = packbf(
                    (cH0 * cp1 + cL0 * sp1) * scale, (cH1 * cp1 + cL1 * sp1) * scale);
            }
        } else {   // mode 2: vT [b,h,d,l] bf16
            __nv_bfloat16* out = (__nv_bfloat16*)outv;
            int h = warp_n0 >> 6;
            long hb = ((long)(b0 * H_ + h)) * HD_;
#pragma unroll
            for (int nj = 0; nj < 8; nj++) {
                int d = nj * 8 + 2 * t;
                float2 bb = *(const float2*)&bias[warp_n0 + d];
                out[(hb + d    ) * L_ + l0m]     = __float2bfloat16(acc[mi][nj][0] + bb.x);
                out[(hb + d + 1) * L_ + l0m]     = __float2bfloat16(acc[mi][nj][1] + bb.y);
                out[(hb + d    ) * L_ + l0m + 8] = __float2bfloat16(acc[mi][nj][2] + bb.x);
                out[(hb + d + 1) * L_ + l0m + 8] = __float2bfloat16(acc[mi][nj][3] + bb.y);
            }
        }
    }
}

// ---------------------------------------------------------------------------
// Flash attention (R11/R13 config + ex2): bf16 m16n8k16 + ldmatrix, cp.async
// double-buffered K/V. Br=128, Bc=64. 128 threads (4 warps), 32 rows/warp,
// cached Q fragments, 2 CTAs/SM. exp via raw ex2 (log2e pre-folded into
// q scale and mask). C=0 softmax, row sums reduced once.
// ---------------------------------------------------------------------------
#define QPITCH 72
#define FQS 0
#define FKS (128*QPITCH*2)               // 18432
#define FVS (FKS + 2*64*QPITCH*2)        // 36864
#define FMS (FVS + 2*64*QPITCH*2)        // 55296
#define FLASH_SMEM (FMS + 64*4)          // 55552 B

__global__ void __launch_bounds__(128, 2) flash_mma(
    const __nv_bfloat16* __restrict__ q, const __nv_bfloat16* __restrict__ k,
    const __nv_bfloat16* __restrict__ vT, const float* __restrict__ mask,
    __nv_bfloat16* __restrict__ ctx)
{
    extern __shared__ __align__(16) char fsm[];
    uint32_t sbu = smem_u32(fsm);
    float* ms = (float*)(fsm + FMS);

    int tid = threadIdx.x, lane = tid & 31, wid = tid >> 5;
    int g = lane >> 2, t = lane & 3;
    int bh = blockIdx.y;
    int b  = bh >> 4, h = bh & (H_ - 1);
    int l0 = blockIdx.x * 128;

    const __nv_bfloat16* qb  = q  + ((long)bh * L_ + l0) * HD_;
    const __nv_bfloat16* kb  = k  + (long)bh * L_ * HD_;
    const __nv_bfloat16* vtb = vT + (long)bh * HD_ * L_;

    auto load_kv = [&](int kt) {
        int st = kt & 1;
        uint32_t kbase = sbu + FKS + (uint32_t)(st * 64 * QPITCH * 2);
        uint32_t vbase = sbu + FVS + (uint32_t)(st * 64 * QPITCH * 2);
#pragma unroll
        for (int i = 0; i < 4; i++) {
            int idx = tid + i * 128;     // 0..511
            int r = idx >> 3, ch = idx & 7;
            uint32_t off = (uint32_t)(r * (QPITCH * 2) + ch * 16);
            CP_ASYNC16(kbase + off, kb + (long)(kt * 64 + r) * HD_ + ch * 8);
            CP_ASYNC16(vbase + off, vtb + (long)r * L_ + kt * 64 + ch * 8);
        }
        CP_COMMIT();
    };

    // Q tile: 128 rows x 8 chunks = 1024 chunks
    {
        uint32_t qbase = sbu + FQS;
#pragma unroll
        for (int i = 0; i < 8; i++) {
            int idx = tid + i * 128;
            int r = idx >> 3, ch = idx & 7;
            CP_ASYNC16(qbase + (uint32_t)(r * (QPITCH * 2) + ch * 16),
                       qb + (long)r * HD_ + ch * 8);
        }
        CP_COMMIT();
    }
    load_kv(0);
    CP_WAIT1();          // Q complete
    __syncthreads();

    // hoist Q A-fragments: two 16-row tiles per warp
    uint32_t aq[2][4][4];
    {
        int arow_off = (lane & 7) + ((lane >> 3) & 1) * 8;
        int acol = (lane >> 4) * 8;
#pragma unroll
        for (int mi = 0; mi < 2; mi++) {
            int arow = wid * 32 + mi * 16 + arow_off;
#pragma unroll
            for (int kc = 0; kc < 4; kc++) {
                uint4 r4 = ldm_x4(sbu + FQS +
                    2u * (uint32_t)(arow * QPITCH + kc * 16 + acol));
                aq[mi][kc][0] = r4.x; aq[mi][kc][1] = r4.y;
                aq[mi][kc][2] = r4.z; aq[mi][kc][3] = r4.w;
            }
        }
    }

    float lp[2][2] = {{0.f, 0.f}, {0.f, 0.f}};   // per-thread row sums
    float o[2][8][4];
#pragma unroll
    for (int mi = 0; mi < 2; mi++)
#pragma unroll
        for (int nj = 0; nj < 8; nj++)
#pragma unroll
            for (int x = 0; x < 4; x++) o[mi][nj][x] = 0.f;

    int brow_off = (lane & 7) + ((lane >> 4) << 3);
    int bcol_off = ((lane >> 3) & 1) * 8;

    const int NT = L_ / 64;
    for (int kt = 0; kt < NT; kt++) {
        __syncthreads();                 // all warps done with buffer (kt+1)&1
        if (tid < 64) ms[tid] = mask[(long)b * L_ + kt * 64 + tid] * LOG2E;
        if (kt + 1 < NT) load_kv(kt + 1);
        else CP_COMMIT();
        CP_WAIT1();                      // tile kt landed
        __syncthreads();

        int st = kt & 1;
        uint32_t ks_base = sbu + FKS + (uint32_t)(st * 64 * QPITCH * 2);
        uint32_t vs_base = sbu + FVS + (uint32_t)(st * 64 * QPITCH * 2);

        // ---- S = Q K^T ----  (each K fragment feeds 2 mi MMAs)
        float s[2][8][4];
#pragma unroll
        for (int mi = 0; mi < 2; mi++)
#pragma unroll
            for (int nj = 0; nj < 8; nj++)
#pragma unroll
                for (int x = 0; x < 4; x++) s[mi][nj][x] = 0.f;
#pragma unroll
        for (int kc = 0; kc < 4; kc++) {
#pragma unroll
            for (int p = 0; p < 4; p++) {
                uint4 bb = ldm_x4(ks_base + 2u * (uint32_t)(
                    (p * 16 + brow_off) * QPITCH + kc * 16 + bcol_off));
#pragma unroll
                for (int mi = 0; mi < 2; mi++) {
                    mma_bf16(s[mi][2 * p],     aq[mi][kc], bb.x, bb.y);
                    mma_bf16(s[mi][2 * p + 1], aq[mi][kc], bb.z, bb.w);
                }
            }
        }

        // ---- softmax numerator: ex2(s + mask'), accumulate row sums ----
        uint32_t pa[2][4][4];
#pragma unroll
        for (int mi = 0; mi < 2; mi++) {
#pragma unroll
            for (int nj = 0; nj < 8; nj++) {
                int c0 = nj * 8 + 2 * t;
                float mk0 = ms[c0], mk1 = ms[c0 + 1];
                s[mi][nj][0] = ex2f(s[mi][nj][0] + mk0);
                s[mi][nj][1] = ex2f(s[mi][nj][1] + mk1);
                s[mi][nj][2] = ex2f(s[mi][nj][2] + mk0);
                s[mi][nj][3] = ex2f(s[mi][nj][3] + mk1);
                lp[mi][0] += s[mi][nj][0] + s[mi][nj][1];
                lp[mi][1] += s[mi][nj][2] + s[mi][nj][3];
            }
#pragma unroll
            for (int kc = 0; kc < 4; kc++) {
                pa[mi][kc][0] = packbf(s[mi][2*kc][0],   s[mi][2*kc][1]);
                pa[mi][kc][1] = packbf(s[mi][2*kc][2],   s[mi][2*kc][3]);
                pa[mi][kc][2] = packbf(s[mi][2*kc+1][0], s[mi][2*kc+1][1]);
                pa[mi][kc][3] = packbf(s[mi][2*kc+1][2], s[mi][2*kc+1][3]);
            }
        }

        // ---- O += P V ----  (each V fragment feeds 2 mi MMAs)
#pragma unroll
        for (int kc = 0; kc < 4; kc++) {
#pragma unroll
            for (int p = 0; p < 4; p++) {
                uint4 bb = ldm_x4(vs_base + 2u * (uint32_t)(
                    (p * 16 + brow_off) * QPITCH + kc * 16 + bcol_off));
#pragma unroll
                for (int mi = 0; mi < 2; mi++) {
                    mma_bf16(o[mi][2 * p],     pa[mi][kc], bb.x, bb.y);
                    mma_bf16(o[mi][2 * p + 1], pa[mi][kc], bb.z, bb.w);
                }
            }
        }
    }

    // final row-sum reduction (once)
#pragma unroll
    for (int mi = 0; mi < 2; mi++) {
#pragma unroll
        for (int half = 0; half < 2; half++) {
            lp[mi][half] += __shfl_xor_sync(0xffffffffu, lp[mi][half], 1);
            lp[mi][half] += __shfl_xor_sync(0xffffffffu, lp[mi][half], 2);
        }
    }

    // epilogue: ctx[b, l, h, d] bf16
#pragma unroll
    for (int mi = 0; mi < 2; mi++) {
        float inv0 = 1.f / lp[mi][0], inv1 = 1.f / lp[mi][1];
        long row0 = (long)b * L_ + l0 + wid * 32 + mi * 16 + g;
        long row1 = row0 + 8;
#pragma unroll
        for (int nj = 0; nj < 8; nj++) {
            int c0 = h * HD_ + nj * 8 + 2 * t;
            *(uint32_t*)&ctx[row0 * D_ + c0] =
                packbf(o[mi][nj][0] * inv0, o[mi][nj][1] * inv0);
            *(uint32_t*)&ctx[row1 * D_ + c0] =
                packbf(o[mi][nj][2] * inv1, o[mi][nj][3] * inv1);
        }
    }
}

// ---------------------------------------------------------------------------
// In-place LayerNorm over last dim (1024).
// ---------------------------------------------------------------------------
__global__ void __launch_bounds__(256) ln_kernel(
    float* __restrict__ io, const float* __restrict__ gamma,
    const float* __restrict__ beta)
{
    __shared__ float ss[8], sq[8];
    __shared__ float s_mu, s_rs;
    int row = blockIdx.x, tid = threadIdx.x;
    float* p = io + (long)row * D_;
    float4 x = *(const float4*)&p[tid * 4];
    float s = x.x + x.y + x.z + x.w;
    float qq = x.x * x.x + x.y * x.y + x.z * x.z + x.w * x.w;
#pragma unroll
    for (int off = 16; off; off >>= 1) {
        s  += __shfl_xor_sync(0xffffffffu, s, off);
        qq += __shfl_xor_sync(0xffffffffu, qq, off);
    }
    int w = tid / 32;
    if ((tid & 31) == 0) { ss[w] = s; sq[w] = qq; }
    __syncthreads();
    if (tid == 0) {
        float S = 0.f, Q = 0.f;
#pragma unroll
        for (int i = 0; i < 8; i++) { S += ss[i]; Q += sq[i]; }
        float mu = S * (1.f / D_);
        float var = Q * (1.f / D_) - mu * mu;
        s_mu = mu;
        s_rs = rsqrtf(var + 1e-12f);
    }
    __syncthreads();
    float mu = s_mu, rs = s_rs;
    float4 gv = *(const float4*)&gamma[tid * 4];
    float4 be = *(const float4*)&beta[tid * 4];
    x.x = (x.x - mu) * rs * gv.x + be.x;
    x.y = (x.y - mu) * rs * gv.y + be.y;
    x.z = (x.z - mu) * rs * gv.z + be.z;
    x.w = (x.w - mu) * rs * gv.w + be.w;
    *(float4*)&p[tid * 4] = x;
}

// ---------------------------------------------------------------------------
extern "C" void kernel_launch(void* const* d_in, const int* in_sizes, int n_in,
                              void* d_out, int out_size)
{
    (void)in_sizes; (void)n_in; (void)out_size;
    const float* X    = (const float*)d_in[0];
    const float* mask = (const float*)d_in[1];
    const float* phi  = (const float*)d_in[2];
    const float* Wq   = (const float*)d_in[3];
    const float* bq   = (const float*)d_in[4];
    const float* Wk   = (const float*)d_in[5];
    const float* bk   = (const float*)d_in[6];
    const float* Wv   = (const float*)d_in[7];
    const float* bv   = (const float*)d_in[8];
    const float* Wo   = (const float*)d_in[9];
    const float* bo   = (const float*)d_in[10];
    const float* gamma= (const float*)d_in[11];
    const float* beta = (const float*)d_in[12];
    float* out = (float*)d_out;

    __nv_bfloat16 *xbf, *wq, *wk, *wv, *wo, *q, *k, *vT, *ctx;
    cudaGetSymbolAddress((void**)&xbf, g_xbf);
    cudaGetSymbolAddress((void**)&wq,  g_wq);
    cudaGetSymbolAddress((void**)&wk,  g_wk);
    cudaGetSymbolAddress((void**)&wv,  g_wv);
    cudaGetSymbolAddress((void**)&wo,  g_wo);
    cudaGetSymbolAddress((void**)&q,   g_q);
    cudaGetSymbolAddress((void**)&k,   g_k);
    cudaGetSymbolAddress((void**)&vT,  g_vT);
    cudaGetSymbolAddress((void**)&ctx, g_ctx);

    cudaFuncSetAttribute(gemm_bf16,
        cudaFuncAttributeMaxDynamicSharedMemorySize, GEMM_SMEM);
    cudaFuncSetAttribute(flash_mma,
        cudaFuncAttributeMaxDynamicSharedMemorySize, FLASH_SMEM);

    // fp32 -> bf16 conversions (X + 4 weights, single launch)
    cvt_all<<<(NX4 + 4*NW4) / 256, 256>>>(X, Wq, Wk, Wv, Wo,
                                          xbf, wq, wk, wv, wo);

    // fused QKV projection (gridDim.z = 3) with rotary / vT epilogues
    gemm_bf16<<<dim3(D_/128, M_/128, 3), 256, GEMM_SMEM>>>(
        xbf, wq, wk, wv, bq, bk, bv, nullptr, phi, q, k, vT, 1);

    // flash attention -> ctx bf16 [b,l,h,d]  (128 threads, 2 CTAs/SM)
    flash_mma<<<dim3(L_/128, B_*H_), 128, FLASH_SMEM>>>(q, k, vT, mask, ctx);

    // O projection + bias + residual(fp32 X) -> d_out
    gemm_bf16<<<dim3(D_/128, M_/128, 1), 256, GEMM_SMEM>>>(
        ctx, wo, nullptr, nullptr, bo, nullptr, nullptr, X, nullptr,
        out, nullptr, nullptr, 0);

    // in-place LayerNorm
    ln_kernel<<<M_, 256>>>(out, gamma, beta);
}